// round 12
// baseline (speedup 1.0000x reference)
#include <cuda_runtime.h>
#include <cuda_fp16.h>
#include <cstdint>
#include <cstddef>

#define NN 131072
#define KK 27
#define FIN 3
#define FOUT 32
#define EPSV 1e-5f

// ---------------- device scratch (no allocation allowed) ----------------
__device__ float  g_z[(size_t)NN * FOUT];
__device__ uint4  g_hh[(size_t)NN * 4];    // per node 64B: fp16 of h[0..31]
__device__ float4 g_x4[(size_t)NN];
__device__ int    g_nbrT[(size_t)KK * NN];
// B fragments (fp16 W): [k][pair0..3][lane] -> {slot2p.b0, slot2p.b1, slot2p+1.b0, slot2p+1.b1}
__device__ uint4  g_wfragH[KK * 4 * 32];

__device__ __forceinline__ uint32_t smem_u32(const void* p) {
    uint32_t a;
    asm("{ .reg .u64 t; cvta.to.shared.u64 t, %1; cvt.u32.u64 %0, t; }" : "=r"(a) : "l"(p));
    return a;
}
__device__ __forceinline__ uint32_t pack_h2(float a, float b) {
    const __half ha = __float2half_rn(a);
    const __half hb = __float2half_rn(b);
    return (uint32_t)__half_as_ushort(ha) | ((uint32_t)__half_as_ushort(hb) << 16);
}
__device__ __forceinline__ void cp16(uint32_t saddr, const void* gaddr) {
    asm volatile("cp.async.cg.shared.global [%0], [%1], 16;" :: "r"(saddr), "l"(gaddr));
}
#define CP_COMMIT() asm volatile("cp.async.commit_group;" ::: "memory")
#define CP_WAIT2()  asm volatile("cp.async.wait_group 2;" ::: "memory")

#define LDSM4(r, addr) \
    asm volatile("ldmatrix.sync.aligned.m8n8.x4.shared.b16 {%0,%1,%2,%3}, [%4];" \
        : "=r"((r)[0]), "=r"((r)[1]), "=r"((r)[2]), "=r"((r)[3]) : "r"(addr))

#define MMA16816(d, a, b0, b1) \
    asm volatile("mma.sync.aligned.m16n8k16.row.col.f32.f16.f16.f32 " \
        "{%0,%1,%2,%3}, {%4,%5,%6,%7}, {%8,%9}, {%0,%1,%2,%3};" \
        : "+f"((d)[0]), "+f"((d)[1]), "+f"((d)[2]), "+f"((d)[3]) \
        : "r"((a)[0]), "r"((a)[1]), "r"((a)[2]), "r"((a)[3]), "r"(b0), "r"(b1))

// ---------------- prep: tiled transpose + x pad + B-fragment image ----------------
__global__ __launch_bounds__(256) void prep_kernel(
    const float* __restrict__ x_feats,
    const int*   __restrict__ nbr,
    const float* __restrict__ w2)
{
    const int tid = threadIdx.x;
    const int b   = blockIdx.x;
    if (b < NN / 256) {
        __shared__ int s[256 * KK];
        const int n0 = b * 256;
        const int* src = nbr + (size_t)n0 * KK;
        #pragma unroll
        for (int i = 0; i < KK; i++) s[tid + i * 256] = src[tid + i * 256];
        {
            const int n = n0 + tid;
            g_x4[n] = make_float4(x_feats[3*n], x_feats[3*n+1], x_feats[3*n+2], 0.0f);
        }
        __syncthreads();
        #pragma unroll 1
        for (int k = 0; k < KK; k++)
            g_nbrT[(size_t)k * NN + n0 + tid] = s[tid * KK + k];
    } else {
        const int i = (b - NN / 256) * 256 + tid;
        if (i < KK * 4 * 32) {
            const int lane = i & 31;
            const int pair = (i >> 5) & 3;
            const int k    = i >> 7;
            uint4 r;
            #pragma unroll
            for (int e = 0; e < 2; e++) {
                const int s     = pair * 2 + e;
                const int kc    = s >> 2;
                const int ntile = s & 3;
                const int o  = ntile * 8 + (lane >> 2);
                const int f0 = kc * 16 + (lane & 3) * 2;
                const uint32_t b0 = pack_h2(w2[(k*32 + f0    )*32 + o],
                                            w2[(k*32 + f0 + 1)*32 + o]);
                const uint32_t b1 = pack_h2(w2[(k*32 + f0 + 8)*32 + o],
                                            w2[(k*32 + f0 + 9)*32 + o]);
                if (e == 0) { r.x = b0; r.y = b1; } else { r.z = b0; r.w = b1; }
            }
            g_wfragH[i] = r;
        }
    }
}

// ---------------- stage 1: M=2 nodes per thread, prefetched gather ----------------
__global__ __launch_bounds__(256) void stage1_kernel(
    const float* __restrict__ z_feats,
    const float* __restrict__ w1,
    const float* __restrict__ bn1_gamma,
    const float* __restrict__ bn1_beta,
    const float* __restrict__ bn1_mean,
    const float* __restrict__ bn1_var,
    const float* __restrict__ mlp_w,
    const float* __restrict__ mlp_b,
    const float* __restrict__ mlp_gamma,
    const float* __restrict__ mlp_beta,
    const float* __restrict__ mlp_mean,
    const float* __restrict__ mlp_var)
{
    __shared__ __align__(16) float w1s[KK * FIN * FOUT];
    __shared__ __align__(16) float mws[FIN * FOUT];
    __shared__ float s1[FOUT], t1[FOUT], s2[FOUT], t2[FOUT], mbs[FOUT];

    const int tid = threadIdx.x;
    for (int i = tid; i < KK * FIN * FOUT; i += 256) w1s[i] = w1[i];
    for (int i = tid; i < FIN * FOUT; i += 256) mws[i] = mlp_w[i];
    if (tid < FOUT) {
        float s = bn1_gamma[tid] * rsqrtf(bn1_var[tid] + EPSV);
        s1[tid] = s;
        t1[tid] = bn1_beta[tid] - bn1_mean[tid] * s;
        float q = mlp_gamma[tid] * rsqrtf(mlp_var[tid] + EPSV);
        s2[tid] = q;
        t2[tid] = mlp_beta[tid] - mlp_mean[tid] * q;
        mbs[tid] = mlp_b[tid];
    }
    __syncthreads();

    const int n = (blockIdx.x * 256 + tid) * 2;

    // ---- point branch (2 nodes) ----
    #pragma unroll
    for (int m = 0; m < 2; m++) {
        float acc[FOUT];
        const float zf0 = z_feats[(size_t)(n+m) * 3 + 0];
        const float zf1 = z_feats[(size_t)(n+m) * 3 + 1];
        const float zf2 = z_feats[(size_t)(n+m) * 3 + 2];
        #pragma unroll
        for (int o = 0; o < FOUT; o++) {
            float v = zf0 * mws[o] + zf1 * mws[FOUT + o] + zf2 * mws[2 * FOUT + o] + mbs[o];
            v = v * s2[o] + t2[o];
            acc[o] = fmaxf(v, 0.0f);
        }
        float4* zp = (float4*)&g_z[(size_t)(n+m) * FOUT];
        #pragma unroll
        for (int i = 0; i < 8; i++)
            zp[i] = make_float4(acc[4*i], acc[4*i+1], acc[4*i+2], acc[4*i+3]);
    }

    // ---- voxel branch stage 1, packed f32x2, M=2 reuse, k+1 prefetch ----
    unsigned long long acc0[16], acc1[16];
    #pragma unroll
    for (int i = 0; i < 16; i++) { acc0[i] = 0ull; acc1[i] = 0ull; }

    int2 jj = *(const int2*)(g_nbrT + n);
    float4 xa = __ldg(&g_x4[jj.x]);
    float4 xb = __ldg(&g_x4[jj.y]);

    #pragma unroll 1
    for (int k = 0; k < KK; k++) {
        const float xs0[3] = {xa.x, xa.y, xa.z};
        const float xs1[3] = {xb.x, xb.y, xb.z};
        if (k + 1 < KK) {
            jj = *(const int2*)(g_nbrT + (size_t)(k + 1) * NN + n);
            xa = __ldg(&g_x4[jj.x]);
            xb = __ldg(&g_x4[jj.y]);
        }
        const double2* w = (const double2*)&w1s[k * FIN * FOUT];
        #pragma unroll
        for (int f = 0; f < FIN; f++) {
            unsigned long long hp0, hp1;
            { unsigned int u = __float_as_uint(xs0[f]);
              asm("mov.b64 %0, {%1, %1};" : "=l"(hp0) : "r"(u)); }
            { unsigned int u = __float_as_uint(xs1[f]);
              asm("mov.b64 %0, {%1, %1};" : "=l"(hp1) : "r"(u)); }
            #pragma unroll
            for (int p = 0; p < 8; p++) {
                double2 wv = w[f * 8 + p];
                unsigned long long w0 = __double_as_longlong(wv.x);
                unsigned long long w1v = __double_as_longlong(wv.y);
                asm("fma.rn.f32x2 %0, %1, %2, %0;" : "+l"(acc0[2*p])   : "l"(hp0), "l"(w0));
                asm("fma.rn.f32x2 %0, %1, %2, %0;" : "+l"(acc0[2*p+1]) : "l"(hp0), "l"(w1v));
                asm("fma.rn.f32x2 %0, %1, %2, %0;" : "+l"(acc1[2*p])   : "l"(hp1), "l"(w0));
                asm("fma.rn.f32x2 %0, %1, %2, %0;" : "+l"(acc1[2*p+1]) : "l"(hp1), "l"(w1v));
            }
        }
    }

    // BN + SiLU, round to fp16, pack 64B rows
    #pragma unroll
    for (int m = 0; m < 2; m++) {
        const unsigned long long* acc = (m == 0) ? acc0 : acc1;
        uint32_t hw[16];
        #pragma unroll
        for (int p = 0; p < 16; p++) {
            const unsigned long long a = acc[p];
            float v0 = __uint_as_float((unsigned int)(a & 0xffffffffull));
            float v1 = __uint_as_float((unsigned int)(a >> 32));
            const int o0 = 2*p, o1 = 2*p + 1;
            v0 = v0 * s1[o0] + t1[o0]; v0 = v0 / (1.0f + __expf(-v0));
            v1 = v1 * s1[o1] + t1[o1]; v1 = v1 / (1.0f + __expf(-v1));
            hw[p] = pack_h2(v0, v1);
        }
        uint4* row = &g_hh[(size_t)(n+m) * 4];
        #pragma unroll
        for (int q = 0; q < 4; q++)
            row[q] = make_uint4(hw[4*q], hw[4*q+1], hw[4*q+2], hw[4*q+3]);
    }
}

// ---------------- stage 2: cp.async depth-2 pipelined mma.sync gather-GEMM ----------
// Per warp: 32 nodes. Triple-buffered smem gather via cp.async (no STS, no reg staging).
#define BUF_BYTES 2560                    // 32 rows x 80B
#define SM_TOTAL2 (8 * 3 * BUF_BYTES)     // 61440

__device__ __forceinline__ void issue_gather(int k, uint32_t dst, int tb, int lane,
                                             int gr, int gc) {
    const int j = __ldg(g_nbrT + (size_t)k * NN + tb + lane);
    #pragma unroll
    for (int r = 0; r < 4; r++) {
        const int row = r * 8 + gr;
        const int jr = __shfl_sync(0xffffffffu, j, row);
        cp16(dst + row * 80 + gc * 16, (const char*)g_hh + ((size_t)jr * 64 + gc * 16));
    }
    CP_COMMIT();
}

__global__ __launch_bounds__(256) void stage2_kernel(
    float* __restrict__ out, size_t half)
{
    extern __shared__ __align__(16) char smem2[];

    const int tid  = threadIdx.x;
    const int warp = tid >> 5;
    const int lane = tid & 31;
    const int tb   = blockIdx.x * 256 + warp * 32;
    const int gr = lane >> 2;
    const int gc = lane & 3;
    const uint32_t sb = smem_u32(smem2) + (uint32_t)warp * 3 * BUF_BYTES;

    float d[2][4][4];
    #pragma unroll
    for (int t = 0; t < 2; t++)
        #pragma unroll
        for (int nt = 0; nt < 4; nt++)
            #pragma unroll
            for (int e = 0; e < 4; e++) d[t][nt][e] = 0.0f;

    // prologue: groups for k=0,1
    issue_gather(0, sb,             tb, lane, gr, gc);
    issue_gather(1, sb + BUF_BYTES, tb, lane, gr, gc);

    #pragma unroll 1
    for (int k = 0; k < KK; k++) {
        // issue gather for k+2 (or empty group to keep the count uniform)
        if (k + 2 < KK)
            issue_gather(k + 2, sb + (uint32_t)((k + 2) % 3) * BUF_BYTES, tb, lane, gr, gc);
        else
            CP_COMMIT();

        // B fragments for this k (4 coalesced LDG.128, L1-resident)
        uint4 bf[4];
        {
            const uint4* wf = g_wfragH + (size_t)k * 128 + lane;
            #pragma unroll
            for (int p = 0; p < 4; p++) bf[p] = __ldg(&wf[p * 32]);
        }

        CP_WAIT2();       // group k complete
        __syncwarp();     // cross-lane visibility of buf k%3

        uint32_t a0[8], a1[8];
        {
            const uint32_t ab = sb + (uint32_t)(k % 3) * BUF_BYTES;
            const uint32_t off = (uint32_t)(lane & 15) * 80 + (uint32_t)((lane >> 4) << 4);
            LDSM4(a0,     ab + off);
            LDSM4(a0 + 4, ab + off + 32);
            LDSM4(a1,     ab + 16 * 80 + off);
            LDSM4(a1 + 4, ab + 16 * 80 + off + 32);
        }

        // 16 MMAs: Ah*Wh for both 16-row tiles, both k-chunks
        #pragma unroll
        for (int nt = 0; nt < 4; nt++) {
            const uint4 p0 = bf[nt >> 1];
            const uint32_t b0x = (nt & 1) ? p0.z : p0.x;
            const uint32_t b0y = (nt & 1) ? p0.w : p0.y;
            const uint4 p1 = bf[(4 + nt) >> 1];
            const uint32_t b1x = (nt & 1) ? p1.z : p1.x;
            const uint32_t b1y = (nt & 1) ? p1.w : p1.y;
            MMA16816(d[0][nt], a0,     b0x, b0y);
            MMA16816(d[0][nt], a0 + 4, b1x, b1y);
            MMA16816(d[1][nt], a1,     b0x, b0y);
            MMA16816(d[1][nt], a1 + 4, b1x, b1y);
        }
    }

    // epilogue: + z, write both output halves
    const int row  = lane >> 2;
    const int colb = (lane & 3) * 2;
    #pragma unroll
    for (int t = 0; t < 2; t++) {
        const int n0 = tb + t * 16 + row;
        const int n1 = n0 + 8;
        #pragma unroll
        for (int nt = 0; nt < 4; nt++) {
            const int col = nt * 8 + colb;
            const float2 z0 = *(const float2*)(g_z + (size_t)n0 * 32 + col);
            const float2 z1 = *(const float2*)(g_z + (size_t)n1 * 32 + col);
            float2 o0 = make_float2(d[t][nt][0] + z0.x, d[t][nt][1] + z0.y);
            float2 o1 = make_float2(d[t][nt][2] + z1.x, d[t][nt][3] + z1.y);
            *(float2*)(out + (size_t)n0 * 32 + col)        = o0;
            *(float2*)(out + half + (size_t)n0 * 32 + col) = o0;
            *(float2*)(out + (size_t)n1 * 32 + col)        = o1;
            *(float2*)(out + half + (size_t)n1 * 32 + col) = o1;
        }
    }
}

// ---------------------------------------------------------------------------
extern "C" void kernel_launch(void* const* d_in, const int* in_sizes, int n_in,
                              void* d_out, int out_size)
{
    const float* x_feats   = (const float*)d_in[0];
    const float* z_feats   = (const float*)d_in[1];
    const int*   nbr_idx   = (const int*)  d_in[2];
    const float* w1        = (const float*)d_in[3];
    const float* bn1_gamma = (const float*)d_in[4];
    const float* bn1_beta  = (const float*)d_in[5];
    const float* bn1_mean  = (const float*)d_in[6];
    const float* bn1_var   = (const float*)d_in[7];
    const float* w2        = (const float*)d_in[8];
    const float* mlp_w     = (const float*)d_in[9];
    const float* mlp_b     = (const float*)d_in[10];
    const float* mlp_gamma = (const float*)d_in[11];
    const float* mlp_beta  = (const float*)d_in[12];
    const float* mlp_mean  = (const float*)d_in[13];
    const float* mlp_var   = (const float*)d_in[14];

    float* out = (float*)d_out;
    const size_t half = (size_t)out_size / 2;

    static bool attr_done = false;
    if (!attr_done) {
        cudaFuncSetAttribute(stage2_kernel,
                             cudaFuncAttributeMaxDynamicSharedMemorySize, SM_TOTAL2);
        attr_done = true;
    }

    prep_kernel<<<NN / 256 + (KK * 128 + 255) / 256, 256>>>(x_feats, nbr_idx, w2);

    stage1_kernel<<<NN / 512, 256>>>(z_feats, w1,
                                     bn1_gamma, bn1_beta, bn1_mean, bn1_var,
                                     mlp_w, mlp_b, mlp_gamma, mlp_beta,
                                     mlp_mean, mlp_var);

    stage2_kernel<<<NN / 256, 256, SM_TOTAL2>>>(out, half);
}

// round 13
// speedup vs baseline: 1.1036x; 1.1036x over previous
#include <cuda_runtime.h>
#include <cuda_fp16.h>
#include <cstdint>
#include <cstddef>

#define NN 131072
#define KK 27
#define FIN 3
#define FOUT 32
#define EPSV 1e-5f

// ---------------- device scratch (no allocation allowed) ----------------
__device__ float  g_z[(size_t)NN * FOUT];
__device__ uint4  g_hh[(size_t)NN * 4];    // per node 64B: fp16 of h[0..31]
__device__ float4 g_x4[(size_t)NN];
__device__ int    g_nbrT[(size_t)KK * NN];
// B fragments (fp16 W): [k][pair0..3][lane] -> {slot2p.b0, slot2p.b1, slot2p+1.b0, slot2p+1.b1}
__device__ uint4  g_wfragH[KK * 4 * 32];

__device__ __forceinline__ uint32_t smem_u32(const void* p) {
    uint32_t a;
    asm("{ .reg .u64 t; cvta.to.shared.u64 t, %1; cvt.u32.u64 %0, t; }" : "=r"(a) : "l"(p));
    return a;
}
__device__ __forceinline__ uint32_t pack_h2(float a, float b) {
    const __half ha = __float2half_rn(a);
    const __half hb = __float2half_rn(b);
    return (uint32_t)__half_as_ushort(ha) | ((uint32_t)__half_as_ushort(hb) << 16);
}

#define LDSM4(r, addr) \
    asm volatile("ldmatrix.sync.aligned.m8n8.x4.shared.b16 {%0,%1,%2,%3}, [%4];" \
        : "=r"((r)[0]), "=r"((r)[1]), "=r"((r)[2]), "=r"((r)[3]) : "r"(addr))

#define MMA16816(d, a, b0, b1) \
    asm volatile("mma.sync.aligned.m16n8k16.row.col.f32.f16.f16.f32 " \
        "{%0,%1,%2,%3}, {%4,%5,%6,%7}, {%8,%9}, {%0,%1,%2,%3};" \
        : "+f"((d)[0]), "+f"((d)[1]), "+f"((d)[2]), "+f"((d)[3]) \
        : "r"((a)[0]), "r"((a)[1]), "r"((a)[2]), "r"((a)[3]), "r"(b0), "r"(b1))

// ---------------- prep: tiled transpose + x pad + B-fragment image ----------------
__global__ __launch_bounds__(256) void prep_kernel(
    const float* __restrict__ x_feats,
    const int*   __restrict__ nbr,
    const float* __restrict__ w2)
{
    const int tid = threadIdx.x;
    const int b   = blockIdx.x;
    if (b < NN / 256) {
        __shared__ int s[256 * KK];
        const int n0 = b * 256;
        const int* src = nbr + (size_t)n0 * KK;
        #pragma unroll
        for (int i = 0; i < KK; i++) s[tid + i * 256] = src[tid + i * 256];
        {
            const int n = n0 + tid;
            g_x4[n] = make_float4(x_feats[3*n], x_feats[3*n+1], x_feats[3*n+2], 0.0f);
        }
        __syncthreads();
        #pragma unroll 1
        for (int k = 0; k < KK; k++)
            g_nbrT[(size_t)k * NN + n0 + tid] = s[tid * KK + k];
    } else {
        const int i = (b - NN / 256) * 256 + tid;
        if (i < KK * 4 * 32) {
            const int lane = i & 31;
            const int pair = (i >> 5) & 3;
            const int k    = i >> 7;
            uint4 r;
            #pragma unroll
            for (int e = 0; e < 2; e++) {
                const int s     = pair * 2 + e;
                const int kc    = s >> 2;
                const int ntile = s & 3;
                const int o  = ntile * 8 + (lane >> 2);
                const int f0 = kc * 16 + (lane & 3) * 2;
                const uint32_t b0 = pack_h2(w2[(k*32 + f0    )*32 + o],
                                            w2[(k*32 + f0 + 1)*32 + o]);
                const uint32_t b1 = pack_h2(w2[(k*32 + f0 + 8)*32 + o],
                                            w2[(k*32 + f0 + 9)*32 + o]);
                if (e == 0) { r.x = b0; r.y = b1; } else { r.z = b0; r.w = b1; }
            }
            g_wfragH[i] = r;
        }
    }
}

// ---------------- stage 1: M=2 nodes per thread, prefetched gather ----------------
__global__ __launch_bounds__(256) void stage1_kernel(
    const float* __restrict__ z_feats,
    const float* __restrict__ w1,
    const float* __restrict__ bn1_gamma,
    const float* __restrict__ bn1_beta,
    const float* __restrict__ bn1_mean,
    const float* __restrict__ bn1_var,
    const float* __restrict__ mlp_w,
    const float* __restrict__ mlp_b,
    const float* __restrict__ mlp_gamma,
    const float* __restrict__ mlp_beta,
    const float* __restrict__ mlp_mean,
    const float* __restrict__ mlp_var)
{
    __shared__ __align__(16) float w1s[KK * FIN * FOUT];
    __shared__ __align__(16) float mws[FIN * FOUT];
    __shared__ float s1[FOUT], t1[FOUT], s2[FOUT], t2[FOUT], mbs[FOUT];

    const int tid = threadIdx.x;
    for (int i = tid; i < KK * FIN * FOUT; i += 256) w1s[i] = w1[i];
    for (int i = tid; i < FIN * FOUT; i += 256) mws[i] = mlp_w[i];
    if (tid < FOUT) {
        float s = bn1_gamma[tid] * rsqrtf(bn1_var[tid] + EPSV);
        s1[tid] = s;
        t1[tid] = bn1_beta[tid] - bn1_mean[tid] * s;
        float q = mlp_gamma[tid] * rsqrtf(mlp_var[tid] + EPSV);
        s2[tid] = q;
        t2[tid] = mlp_beta[tid] - mlp_mean[tid] * q;
        mbs[tid] = mlp_b[tid];
    }
    __syncthreads();

    const int n = (blockIdx.x * 256 + tid) * 2;

    // ---- point branch (2 nodes) ----
    #pragma unroll
    for (int m = 0; m < 2; m++) {
        float acc[FOUT];
        const float zf0 = z_feats[(size_t)(n+m) * 3 + 0];
        const float zf1 = z_feats[(size_t)(n+m) * 3 + 1];
        const float zf2 = z_feats[(size_t)(n+m) * 3 + 2];
        #pragma unroll
        for (int o = 0; o < FOUT; o++) {
            float v = zf0 * mws[o] + zf1 * mws[FOUT + o] + zf2 * mws[2 * FOUT + o] + mbs[o];
            v = v * s2[o] + t2[o];
            acc[o] = fmaxf(v, 0.0f);
        }
        float4* zp = (float4*)&g_z[(size_t)(n+m) * FOUT];
        #pragma unroll
        for (int i = 0; i < 8; i++)
            zp[i] = make_float4(acc[4*i], acc[4*i+1], acc[4*i+2], acc[4*i+3]);
    }

    // ---- voxel branch stage 1, packed f32x2, M=2 reuse, k+1 prefetch ----
    unsigned long long acc0[16], acc1[16];
    #pragma unroll
    for (int i = 0; i < 16; i++) { acc0[i] = 0ull; acc1[i] = 0ull; }

    int2 jj = *(const int2*)(g_nbrT + n);
    float4 xa = __ldg(&g_x4[jj.x]);
    float4 xb = __ldg(&g_x4[jj.y]);

    #pragma unroll 1
    for (int k = 0; k < KK; k++) {
        const float xs0[3] = {xa.x, xa.y, xa.z};
        const float xs1[3] = {xb.x, xb.y, xb.z};
        if (k + 1 < KK) {
            jj = *(const int2*)(g_nbrT + (size_t)(k + 1) * NN + n);
            xa = __ldg(&g_x4[jj.x]);
            xb = __ldg(&g_x4[jj.y]);
        }
        const double2* w = (const double2*)&w1s[k * FIN * FOUT];
        #pragma unroll
        for (int f = 0; f < FIN; f++) {
            unsigned long long hp0, hp1;
            { unsigned int u = __float_as_uint(xs0[f]);
              asm("mov.b64 %0, {%1, %1};" : "=l"(hp0) : "r"(u)); }
            { unsigned int u = __float_as_uint(xs1[f]);
              asm("mov.b64 %0, {%1, %1};" : "=l"(hp1) : "r"(u)); }
            #pragma unroll
            for (int p = 0; p < 8; p++) {
                double2 wv = w[f * 8 + p];
                unsigned long long w0 = __double_as_longlong(wv.x);
                unsigned long long w1v = __double_as_longlong(wv.y);
                asm("fma.rn.f32x2 %0, %1, %2, %0;" : "+l"(acc0[2*p])   : "l"(hp0), "l"(w0));
                asm("fma.rn.f32x2 %0, %1, %2, %0;" : "+l"(acc0[2*p+1]) : "l"(hp0), "l"(w1v));
                asm("fma.rn.f32x2 %0, %1, %2, %0;" : "+l"(acc1[2*p])   : "l"(hp1), "l"(w0));
                asm("fma.rn.f32x2 %0, %1, %2, %0;" : "+l"(acc1[2*p+1]) : "l"(hp1), "l"(w1v));
            }
        }
    }

    // BN + SiLU, round to fp16, pack 64B rows
    #pragma unroll
    for (int m = 0; m < 2; m++) {
        const unsigned long long* acc = (m == 0) ? acc0 : acc1;
        uint32_t hw[16];
        #pragma unroll
        for (int p = 0; p < 16; p++) {
            const unsigned long long a = acc[p];
            float v0 = __uint_as_float((unsigned int)(a & 0xffffffffull));
            float v1 = __uint_as_float((unsigned int)(a >> 32));
            const int o0 = 2*p, o1 = 2*p + 1;
            v0 = v0 * s1[o0] + t1[o0]; v0 = v0 / (1.0f + __expf(-v0));
            v1 = v1 * s1[o1] + t1[o1]; v1 = v1 / (1.0f + __expf(-v1));
            hw[p] = pack_h2(v0, v1);
        }
        uint4* row = &g_hh[(size_t)(n+m) * 4];
        #pragma unroll
        for (int q = 0; q < 4; q++)
            row[q] = make_uint4(hw[4*q], hw[4*q+1], hw[4*q+2], hw[4*q+3]);
    }
}

// ---------------- stage 2: depth-2 register-pipelined mma.sync gather-GEMM ----------
// 128-thread CTAs (4 warps), M=32/warp. No shfl: direct per-lane index loads,
// prefetched 2 iterations ahead; row LDG at k for use at k+2 (full iter before STS).
#define BUF_BYTES 2560                    // 32 rows x 80B
#define NWARP2 4
#define SM_TOTAL2 (NWARP2 * 2 * BUF_BYTES)  // 20480

__global__ __launch_bounds__(128) void stage2_kernel(
    float* __restrict__ out, size_t half)
{
    __shared__ __align__(16) char smem2[SM_TOTAL2];

    const int tid  = threadIdx.x;
    const int warp = tid >> 5;
    const int lane = tid & 31;
    const int tb   = blockIdx.x * (NWARP2 * 32) + warp * 32;
    const int gr = lane >> 2;                 // row-within-group 0..7
    const int gc = lane & 3;                  // 16B chunk 0..3
    const uint32_t sb = smem_u32(smem2) + (uint32_t)warp * 2 * BUF_BYTES;

    float d[2][4][4];
    #pragma unroll
    for (int t = 0; t < 2; t++)
        #pragma unroll
        for (int nt = 0; nt < 4; nt++)
            #pragma unroll
            for (int e = 0; e < 4; e++) d[t][nt][e] = 0.0f;

    // lane's 4 row slots: rows gr, 8+gr, 16+gr, 24+gr
    // prologue: idx k=0,1 ; gather k=0 ; STS -> buf0 ; gather k=1 ; idx k=2
    int jn[4];      // indices for gather of row set "next"
    uint4 v[4];     // gathered rows awaiting STS
    {
        int j0[4];
        #pragma unroll
        for (int r = 0; r < 4; r++)
            j0[r] = __ldg(g_nbrT + tb + r * 8 + gr);
        #pragma unroll
        for (int r = 0; r < 4; r++)
            jn[r] = __ldg(g_nbrT + (size_t)1 * NN + tb + r * 8 + gr);
        #pragma unroll
        for (int r = 0; r < 4; r++)
            v[r] = __ldg(&g_hh[(size_t)j0[r] * 4 + gc]);
        #pragma unroll
        for (int r = 0; r < 4; r++)
            *(uint4*)(smem2 + (warp * 2 * BUF_BYTES) + (r * 8 + gr) * 80 + gc * 16) = v[r];
        // gather rows k=1
        #pragma unroll
        for (int r = 0; r < 4; r++)
            v[r] = __ldg(&g_hh[(size_t)jn[r] * 4 + gc]);
        #pragma unroll
        for (int r = 0; r < 4; r++)
            jn[r] = __ldg(g_nbrT + (size_t)2 * NN + tb + r * 8 + gr);
    }

    #pragma unroll 2
    for (int k = 0; k < KK; k++) {
        // STS rows k+1 (LDG'd one full iteration ago) into buf[(k+1)&1]
        if (k + 1 < KK) {
            char* dst = smem2 + warp * 2 * BUF_BYTES + ((k + 1) & 1) * BUF_BYTES;
            #pragma unroll
            for (int r = 0; r < 4; r++)
                *(uint4*)(dst + (r * 8 + gr) * 80 + gc * 16) = v[r];
        }
        // issue gather rows k+2 (indices prefetched), then idx k+3
        if (k + 2 < KK) {
            #pragma unroll
            for (int r = 0; r < 4; r++)
                v[r] = __ldg(&g_hh[(size_t)jn[r] * 4 + gc]);
            if (k + 3 < KK) {
                #pragma unroll
                for (int r = 0; r < 4; r++)
                    jn[r] = __ldg(g_nbrT + (size_t)(k + 3) * NN + tb + r * 8 + gr);
            }
        }

        // B fragments for this k (4 coalesced LDG.128, L1-resident)
        uint4 bf[4];
        {
            const uint4* wf = g_wfragH + (size_t)k * 128 + lane;
            #pragma unroll
            for (int p = 0; p < 4; p++) bf[p] = __ldg(&wf[p * 32]);
        }

        __syncwarp();    // make last iteration's STS (rows k) visible for LDSM

        uint32_t a0[8], a1[8];
        {
            const uint32_t ab = sb + (uint32_t)(k & 1) * BUF_BYTES;
            const uint32_t off = (uint32_t)(lane & 15) * 80 + (uint32_t)((lane >> 4) << 4);
            LDSM4(a0,     ab + off);
            LDSM4(a0 + 4, ab + off + 32);
            LDSM4(a1,     ab + 16 * 80 + off);
            LDSM4(a1 + 4, ab + 16 * 80 + off + 32);
        }

        // 16 MMAs: Ah*Wh for both 16-row tiles, both k-chunks
        #pragma unroll
        for (int nt = 0; nt < 4; nt++) {
            const uint4 p0 = bf[nt >> 1];
            const uint32_t b0x = (nt & 1) ? p0.z : p0.x;
            const uint32_t b0y = (nt & 1) ? p0.w : p0.y;
            const uint4 p1 = bf[(4 + nt) >> 1];
            const uint32_t b1x = (nt & 1) ? p1.z : p1.x;
            const uint32_t b1y = (nt & 1) ? p1.w : p1.y;
            MMA16816(d[0][nt], a0,     b0x, b0y);
            MMA16816(d[0][nt], a0 + 4, b1x, b1y);
            MMA16816(d[1][nt], a1,     b0x, b0y);
            MMA16816(d[1][nt], a1 + 4, b1x, b1y);
        }
        __syncwarp();    // LDSM of buf[k&1] done before next iter's STS overwrites it
    }

    // epilogue: + z, write both output halves
    const int row  = lane >> 2;
    const int colb = (lane & 3) * 2;
    #pragma unroll
    for (int t = 0; t < 2; t++) {
        const int n0 = tb + t * 16 + row;
        const int n1 = n0 + 8;
        #pragma unroll
        for (int nt = 0; nt < 4; nt++) {
            const int col = nt * 8 + colb;
            const float2 z0 = *(const float2*)(g_z + (size_t)n0 * 32 + col);
            const float2 z1 = *(const float2*)(g_z + (size_t)n1 * 32 + col);
            float2 o0 = make_float2(d[t][nt][0] + z0.x, d[t][nt][1] + z0.y);
            float2 o1 = make_float2(d[t][nt][2] + z1.x, d[t][nt][3] + z1.y);
            *(float2*)(out + (size_t)n0 * 32 + col)        = o0;
            *(float2*)(out + half + (size_t)n0 * 32 + col) = o0;
            *(float2*)(out + (size_t)n1 * 32 + col)        = o1;
            *(float2*)(out + half + (size_t)n1 * 32 + col) = o1;
        }
    }
}

// ---------------------------------------------------------------------------
extern "C" void kernel_launch(void* const* d_in, const int* in_sizes, int n_in,
                              void* d_out, int out_size)
{
    const float* x_feats   = (const float*)d_in[0];
    const float* z_feats   = (const float*)d_in[1];
    const int*   nbr_idx   = (const int*)  d_in[2];
    const float* w1        = (const float*)d_in[3];
    const float* bn1_gamma = (const float*)d_in[4];
    const float* bn1_beta  = (const float*)d_in[5];
    const float* bn1_mean  = (const float*)d_in[6];
    const float* bn1_var   = (const float*)d_in[7];
    const float* w2        = (const float*)d_in[8];
    const float* mlp_w     = (const float*)d_in[9];
    const float* mlp_b     = (const float*)d_in[10];
    const float* mlp_gamma = (const float*)d_in[11];
    const float* mlp_beta  = (const float*)d_in[12];
    const float* mlp_mean  = (const float*)d_in[13];
    const float* mlp_var   = (const float*)d_in[14];

    float* out = (float*)d_out;
    const size_t half = (size_t)out_size / 2;

    prep_kernel<<<NN / 256 + (KK * 128 + 255) / 256, 256>>>(x_feats, nbr_idx, w2);

    stage1_kernel<<<NN / 512, 256>>>(z_feats, w1,
                                     bn1_gamma, bn1_beta, bn1_mean, bn1_var,
                                     mlp_w, mlp_b, mlp_gamma, mlp_beta,
                                     mlp_mean, mlp_var);

    stage2_kernel<<<NN / (NWARP2 * 32), 128>>>(out, half);
}

// round 14
// speedup vs baseline: 1.1792x; 1.0685x over previous
#include <cuda_runtime.h>
#include <cuda_fp16.h>
#include <cstdint>
#include <cstddef>

#define NN 131072
#define KK 27
#define FIN 3
#define FOUT 32
#define EPSV 1e-5f

// ---------------- device scratch (no allocation allowed) ----------------
__device__ float  g_z[(size_t)NN * FOUT];
// per node 64B of fp16 h, PRE-PERMUTED into mma A-fragment byte order:
// 8B group g (g=4h+m, h=colhalf, m=0..3) holds cols {16h+2m, 16h+2m+1, 16h+2m+8, 16h+2m+9}
__device__ uint4  g_hh[(size_t)NN * 4];
__device__ float4 g_x4[(size_t)NN];
__device__ int    g_nbrT[(size_t)KK * NN];
// B fragments (fp16 W): [k][pair0..3][lane] -> {slot2p.b0, slot2p.b1, slot2p+1.b0, slot2p+1.b1}
__device__ uint4  g_wfragH[KK * 4 * 32];

__device__ __forceinline__ uint32_t pack_h2(float a, float b) {
    const __half ha = __float2half_rn(a);
    const __half hb = __float2half_rn(b);
    return (uint32_t)__half_as_ushort(ha) | ((uint32_t)__half_as_ushort(hb) << 16);
}

#define MMA16816(d, a0, a1, a2, a3, b0, b1) \
    asm volatile("mma.sync.aligned.m16n8k16.row.col.f32.f16.f16.f32 " \
        "{%0,%1,%2,%3}, {%4,%5,%6,%7}, {%8,%9}, {%0,%1,%2,%3};" \
        : "+f"((d)[0]), "+f"((d)[1]), "+f"((d)[2]), "+f"((d)[3]) \
        : "r"(a0), "r"(a1), "r"(a2), "r"(a3), "r"(b0), "r"(b1))

// ---------------- prep: tiled transpose + x pad + B-fragment image ----------------
__global__ __launch_bounds__(256) void prep_kernel(
    const float* __restrict__ x_feats,
    const int*   __restrict__ nbr,
    const float* __restrict__ w2)
{
    const int tid = threadIdx.x;
    const int b   = blockIdx.x;
    if (b < NN / 256) {
        __shared__ int s[256 * KK];
        const int n0 = b * 256;
        const int* src = nbr + (size_t)n0 * KK;
        #pragma unroll
        for (int i = 0; i < KK; i++) s[tid + i * 256] = src[tid + i * 256];
        {
            const int n = n0 + tid;
            g_x4[n] = make_float4(x_feats[3*n], x_feats[3*n+1], x_feats[3*n+2], 0.0f);
        }
        __syncthreads();
        #pragma unroll 1
        for (int k = 0; k < KK; k++)
            g_nbrT[(size_t)k * NN + n0 + tid] = s[tid * KK + k];
    } else {
        const int i = (b - NN / 256) * 256 + tid;
        if (i < KK * 4 * 32) {
            const int lane = i & 31;
            const int pair = (i >> 5) & 3;
            const int k    = i >> 7;
            uint4 r;
            #pragma unroll
            for (int e = 0; e < 2; e++) {
                const int s     = pair * 2 + e;
                const int kc    = s >> 2;
                const int ntile = s & 3;
                const int o  = ntile * 8 + (lane >> 2);
                const int f0 = kc * 16 + (lane & 3) * 2;
                const uint32_t b0 = pack_h2(w2[(k*32 + f0    )*32 + o],
                                            w2[(k*32 + f0 + 1)*32 + o]);
                const uint32_t b1 = pack_h2(w2[(k*32 + f0 + 8)*32 + o],
                                            w2[(k*32 + f0 + 9)*32 + o]);
                if (e == 0) { r.x = b0; r.y = b1; } else { r.z = b0; r.w = b1; }
            }
            g_wfragH[i] = r;
        }
    }
}

// ---------------- stage 1: M=2 nodes per thread, prefetched gather ----------------
__global__ __launch_bounds__(256) void stage1_kernel(
    const float* __restrict__ z_feats,
    const float* __restrict__ w1,
    const float* __restrict__ bn1_gamma,
    const float* __restrict__ bn1_beta,
    const float* __restrict__ bn1_mean,
    const float* __restrict__ bn1_var,
    const float* __restrict__ mlp_w,
    const float* __restrict__ mlp_b,
    const float* __restrict__ mlp_gamma,
    const float* __restrict__ mlp_beta,
    const float* __restrict__ mlp_mean,
    const float* __restrict__ mlp_var)
{
    __shared__ __align__(16) float w1s[KK * FIN * FOUT];
    __shared__ __align__(16) float mws[FIN * FOUT];
    __shared__ float s1[FOUT], t1[FOUT], s2[FOUT], t2[FOUT], mbs[FOUT];

    const int tid = threadIdx.x;
    for (int i = tid; i < KK * FIN * FOUT; i += 256) w1s[i] = w1[i];
    for (int i = tid; i < FIN * FOUT; i += 256) mws[i] = mlp_w[i];
    if (tid < FOUT) {
        float s = bn1_gamma[tid] * rsqrtf(bn1_var[tid] + EPSV);
        s1[tid] = s;
        t1[tid] = bn1_beta[tid] - bn1_mean[tid] * s;
        float q = mlp_gamma[tid] * rsqrtf(mlp_var[tid] + EPSV);
        s2[tid] = q;
        t2[tid] = mlp_beta[tid] - mlp_mean[tid] * q;
        mbs[tid] = mlp_b[tid];
    }
    __syncthreads();

    const int n = (blockIdx.x * 256 + tid) * 2;

    // ---- point branch (2 nodes) ----
    #pragma unroll
    for (int m = 0; m < 2; m++) {
        float acc[FOUT];
        const float zf0 = z_feats[(size_t)(n+m) * 3 + 0];
        const float zf1 = z_feats[(size_t)(n+m) * 3 + 1];
        const float zf2 = z_feats[(size_t)(n+m) * 3 + 2];
        #pragma unroll
        for (int o = 0; o < FOUT; o++) {
            float v = zf0 * mws[o] + zf1 * mws[FOUT + o] + zf2 * mws[2 * FOUT + o] + mbs[o];
            v = v * s2[o] + t2[o];
            acc[o] = fmaxf(v, 0.0f);
        }
        float4* zp = (float4*)&g_z[(size_t)(n+m) * FOUT];
        #pragma unroll
        for (int i = 0; i < 8; i++)
            zp[i] = make_float4(acc[4*i], acc[4*i+1], acc[4*i+2], acc[4*i+3]);
    }

    // ---- voxel branch stage 1, packed f32x2, M=2 reuse, k+1 prefetch ----
    unsigned long long acc0[16], acc1[16];
    #pragma unroll
    for (int i = 0; i < 16; i++) { acc0[i] = 0ull; acc1[i] = 0ull; }

    int2 jj = *(const int2*)(g_nbrT + n);
    float4 xa = __ldg(&g_x4[jj.x]);
    float4 xb = __ldg(&g_x4[jj.y]);

    #pragma unroll 1
    for (int k = 0; k < KK; k++) {
        const float xs0[3] = {xa.x, xa.y, xa.z};
        const float xs1[3] = {xb.x, xb.y, xb.z};
        if (k + 1 < KK) {
            jj = *(const int2*)(g_nbrT + (size_t)(k + 1) * NN + n);
            xa = __ldg(&g_x4[jj.x]);
            xb = __ldg(&g_x4[jj.y]);
        }
        const double2* w = (const double2*)&w1s[k * FIN * FOUT];
        #pragma unroll
        for (int f = 0; f < FIN; f++) {
            unsigned long long hp0, hp1;
            { unsigned int u = __float_as_uint(xs0[f]);
              asm("mov.b64 %0, {%1, %1};" : "=l"(hp0) : "r"(u)); }
            { unsigned int u = __float_as_uint(xs1[f]);
              asm("mov.b64 %0, {%1, %1};" : "=l"(hp1) : "r"(u)); }
            #pragma unroll
            for (int p = 0; p < 8; p++) {
                double2 wv = w[f * 8 + p];
                unsigned long long w0 = __double_as_longlong(wv.x);
                unsigned long long w1v = __double_as_longlong(wv.y);
                asm("fma.rn.f32x2 %0, %1, %2, %0;" : "+l"(acc0[2*p])   : "l"(hp0), "l"(w0));
                asm("fma.rn.f32x2 %0, %1, %2, %0;" : "+l"(acc0[2*p+1]) : "l"(hp0), "l"(w1v));
                asm("fma.rn.f32x2 %0, %1, %2, %0;" : "+l"(acc1[2*p])   : "l"(hp1), "l"(w0));
                asm("fma.rn.f32x2 %0, %1, %2, %0;" : "+l"(acc1[2*p+1]) : "l"(hp1), "l"(w1v));
            }
        }
    }

    // BN + SiLU, round to fp16, write PERMUTED fragment-order 64B rows:
    // q0={hw0,hw4,hw1,hw5} q1={hw2,hw6,hw3,hw7} q2={hw8,hw12,hw9,hw13} q3={hw10,hw14,hw11,hw15}
    #pragma unroll
    for (int m = 0; m < 2; m++) {
        const unsigned long long* acc = (m == 0) ? acc0 : acc1;
        uint32_t hw[16];
        #pragma unroll
        for (int p = 0; p < 16; p++) {
            const unsigned long long a = acc[p];
            float v0 = __uint_as_float((unsigned int)(a & 0xffffffffull));
            float v1 = __uint_as_float((unsigned int)(a >> 32));
            const int o0 = 2*p, o1 = 2*p + 1;
            v0 = v0 * s1[o0] + t1[o0]; v0 = v0 / (1.0f + __expf(-v0));
            v1 = v1 * s1[o1] + t1[o1]; v1 = v1 / (1.0f + __expf(-v1));
            hw[p] = pack_h2(v0, v1);
        }
        uint4* row = &g_hh[(size_t)(n+m) * 4];
        row[0] = make_uint4(hw[0],  hw[4],  hw[1],  hw[5]);
        row[1] = make_uint4(hw[2],  hw[6],  hw[3],  hw[7]);
        row[2] = make_uint4(hw[8],  hw[12], hw[9],  hw[13]);
        row[3] = make_uint4(hw[10], hw[14], hw[11], hw[15]);
    }
}

// ---------------- stage 2: direct-fragment-LDG mma.sync gather-GEMM ----------------
// No smem, no ldmatrix, no syncwarp. Lane (r=lane>>2, m=lane&3) loads its A-fragment
// words straight from permuted g_hh rows: per 16-row tile t and col-half h, two LDG.64
// give (a0,a2) from row j[2t] and (a1,a3) from row j[2t+1] at byte (4h+m)*8.
// Double-buffered in registers, indices prefetched one k ahead.

__device__ __forceinline__ void load_rows(uint32_t A[16], const int j[4], int m) {
    #pragma unroll
    for (int t = 0; t < 2; t++) {
        const char* p0 = (const char*)g_hh + ((size_t)j[2*t]     << 6);
        const char* p1 = (const char*)g_hh + ((size_t)j[2*t + 1] << 6);
        uint2 v;
        v = __ldg((const uint2*)(p0 + m * 8));       A[8*t+0] = v.x; A[8*t+2] = v.y;
        v = __ldg((const uint2*)(p1 + m * 8));       A[8*t+1] = v.x; A[8*t+3] = v.y;
        v = __ldg((const uint2*)(p0 + 32 + m * 8));  A[8*t+4] = v.x; A[8*t+6] = v.y;
        v = __ldg((const uint2*)(p1 + 32 + m * 8));  A[8*t+5] = v.x; A[8*t+7] = v.y;
    }
}

__global__ __launch_bounds__(128) void stage2_kernel(
    float* __restrict__ out, size_t half)
{
    const int tid  = threadIdx.x;
    const int warp = tid >> 5;
    const int lane = tid & 31;
    const int tb   = blockIdx.x * 128 + warp * 32;
    const int r = lane >> 2;
    const int m = lane & 3;

    float d[2][4][4];
    #pragma unroll
    for (int t = 0; t < 2; t++)
        #pragma unroll
        for (int nt = 0; nt < 4; nt++)
            #pragma unroll
            for (int e = 0; e < 4; e++) d[t][nt][e] = 0.0f;

    // prologue: idx k=0, idx k=1, A-rows k=0
    int jn[4];
    uint32_t A[2][16];
    {
        int jc[4];
        #pragma unroll
        for (int s = 0; s < 4; s++) jc[s] = __ldg(g_nbrT + tb + s * 8 + r);
        #pragma unroll
        for (int s = 0; s < 4; s++) jn[s] = __ldg(g_nbrT + (size_t)NN + tb + s * 8 + r);
        load_rows(A[0], jc, m);
    }

    #pragma unroll 2
    for (int k = 0; k < KK; k++) {
        const int cur = k & 1;
        // issue A-row loads for k+1 (indices already in jn), then idx for k+2
        if (k + 1 < KK) {
            load_rows(A[cur ^ 1], jn, m);
            if (k + 2 < KK) {
                #pragma unroll
                for (int s = 0; s < 4; s++)
                    jn[s] = __ldg(g_nbrT + (size_t)(k + 2) * NN + tb + s * 8 + r);
            }
        }

        // B fragments for this k (4 coalesced LDG.128, L1-resident)
        uint4 bf[4];
        {
            const uint4* wf = g_wfragH + (size_t)k * 128 + lane;
            #pragma unroll
            for (int p = 0; p < 4; p++) bf[p] = __ldg(&wf[p * 32]);
        }

        // 16 MMAs on A[cur]
        #pragma unroll
        for (int nt = 0; nt < 4; nt++) {
            const uint4 p0 = bf[nt >> 1];
            const uint32_t b0x = (nt & 1) ? p0.z : p0.x;
            const uint32_t b0y = (nt & 1) ? p0.w : p0.y;
            const uint4 p1 = bf[(4 + nt) >> 1];
            const uint32_t b1x = (nt & 1) ? p1.z : p1.x;
            const uint32_t b1y = (nt & 1) ? p1.w : p1.y;
            #pragma unroll
            for (int t = 0; t < 2; t++) {
                MMA16816(d[t][nt], A[cur][8*t+0], A[cur][8*t+1], A[cur][8*t+2], A[cur][8*t+3], b0x, b0y);
                MMA16816(d[t][nt], A[cur][8*t+4], A[cur][8*t+5], A[cur][8*t+6], A[cur][8*t+7], b1x, b1y);
            }
        }
    }

    // epilogue: + z, write both output halves
    const int row  = lane >> 2;
    const int colb = (lane & 3) * 2;
    #pragma unroll
    for (int t = 0; t < 2; t++) {
        const int n0 = tb + t * 16 + row;
        const int n1 = n0 + 8;
        #pragma unroll
        for (int nt = 0; nt < 4; nt++) {
            const int col = nt * 8 + colb;
            const float2 z0 = *(const float2*)(g_z + (size_t)n0 * 32 + col);
            const float2 z1 = *(const float2*)(g_z + (size_t)n1 * 32 + col);
            float2 o0 = make_float2(d[t][nt][0] + z0.x, d[t][nt][1] + z0.y);
            float2 o1 = make_float2(d[t][nt][2] + z1.x, d[t][nt][3] + z1.y);
            *(float2*)(out + (size_t)n0 * 32 + col)        = o0;
            *(float2*)(out + half + (size_t)n0 * 32 + col) = o0;
            *(float2*)(out + (size_t)n1 * 32 + col)        = o1;
            *(float2*)(out + half + (size_t)n1 * 32 + col) = o1;
        }
    }
}

// ---------------------------------------------------------------------------
extern "C" void kernel_launch(void* const* d_in, const int* in_sizes, int n_in,
                              void* d_out, int out_size)
{
    const float* x_feats   = (const float*)d_in[0];
    const float* z_feats   = (const float*)d_in[1];
    const int*   nbr_idx   = (const int*)  d_in[2];
    const float* w1        = (const float*)d_in[3];
    const float* bn1_gamma = (const float*)d_in[4];
    const float* bn1_beta  = (const float*)d_in[5];
    const float* bn1_mean  = (const float*)d_in[6];
    const float* bn1_var   = (const float*)d_in[7];
    const float* w2        = (const float*)d_in[8];
    const float* mlp_w     = (const float*)d_in[9];
    const float* mlp_b     = (const float*)d_in[10];
    const float* mlp_gamma = (const float*)d_in[11];
    const float* mlp_beta  = (const float*)d_in[12];
    const float* mlp_mean  = (const float*)d_in[13];
    const float* mlp_var   = (const float*)d_in[14];

    float* out = (float*)d_out;
    const size_t half = (size_t)out_size / 2;

    prep_kernel<<<NN / 256 + (KK * 128 + 255) / 256, 256>>>(x_feats, nbr_idx, w2);

    stage1_kernel<<<NN / 512, 256>>>(z_feats, w1,
                                     bn1_gamma, bn1_beta, bn1_mean, bn1_var,
                                     mlp_w, mlp_b, mlp_gamma, mlp_beta,
                                     mlp_mean, mlp_var);

    stage2_kernel<<<NN / 128, 128>>>(out, half);
}

// round 16
// speedup vs baseline: 1.3087x; 1.1098x over previous
#include <cuda_runtime.h>
#include <cuda_fp16.h>
#include <cstdint>
#include <cstddef>

#define NN 131072
#define KK 27
#define FIN 3
#define FOUT 32
#define EPSV 1e-5f

// ---------------- device scratch (no allocation allowed) ----------------
__device__ float  g_z[(size_t)NN * FOUT];
// per node 64B of fp16 h, PRE-PERMUTED: 16B chunk m (m=0..3) = {hw[m], hw[m+4], hw[m+8], hw[m+12]}
// where hw[p] packs cols {2p, 2p+1}. One LDG.128 at chunk m gives lane m its
// (a0,a2) words for BOTH k-chunks of that row.
__device__ uint4  g_hh[(size_t)NN * 4];
__device__ float4 g_x4[(size_t)NN];
__device__ int    g_nbrT[(size_t)KK * NN];
// B fragments (fp16 W): [k][pair0..3][lane] -> {slot2p.b0, slot2p.b1, slot2p+1.b0, slot2p+1.b1}
__device__ uint4  g_wfragH[KK * 4 * 32];

__device__ __forceinline__ uint32_t pack_h2(float a, float b) {
    const __half ha = __float2half_rn(a);
    const __half hb = __float2half_rn(b);
    return (uint32_t)__half_as_ushort(ha) | ((uint32_t)__half_as_ushort(hb) << 16);
}

#define MMA16816(d, a0, a1, a2, a3, b0, b1) \
    asm volatile("mma.sync.aligned.m16n8k16.row.col.f32.f16.f16.f32 " \
        "{%0,%1,%2,%3}, {%4,%5,%6,%7}, {%8,%9}, {%0,%1,%2,%3};" \
        : "+f"((d)[0]), "+f"((d)[1]), "+f"((d)[2]), "+f"((d)[3]) \
        : "r"(a0), "r"(a1), "r"(a2), "r"(a3), "r"(b0), "r"(b1))

// ---------------- prep: tiled transpose + x pad + B-fragment image ----------------
__global__ __launch_bounds__(256) void prep_kernel(
    const float* __restrict__ x_feats,
    const int*   __restrict__ nbr,
    const float* __restrict__ w2)
{
    const int tid = threadIdx.x;
    const int b   = blockIdx.x;
    if (b < NN / 256) {
        __shared__ int s[256 * KK];
        const int n0 = b * 256;
        const int* src = nbr + (size_t)n0 * KK;
        #pragma unroll
        for (int i = 0; i < KK; i++) s[tid + i * 256] = src[tid + i * 256];
        {
            const int n = n0 + tid;
            g_x4[n] = make_float4(x_feats[3*n], x_feats[3*n+1], x_feats[3*n+2], 0.0f);
        }
        __syncthreads();
        #pragma unroll 1
        for (int k = 0; k < KK; k++)
            g_nbrT[(size_t)k * NN + n0 + tid] = s[tid * KK + k];
    } else {
        const int i = (b - NN / 256) * 256 + tid;
        if (i < KK * 4 * 32) {
            const int lane = i & 31;
            const int pair = (i >> 5) & 3;
            const int k    = i >> 7;
            uint4 r;
            #pragma unroll
            for (int e = 0; e < 2; e++) {
                const int s     = pair * 2 + e;
                const int kc    = s >> 2;
                const int ntile = s & 3;
                const int o  = ntile * 8 + (lane >> 2);
                const int f0 = kc * 16 + (lane & 3) * 2;
                const uint32_t b0 = pack_h2(w2[(k*32 + f0    )*32 + o],
                                            w2[(k*32 + f0 + 1)*32 + o]);
                const uint32_t b1 = pack_h2(w2[(k*32 + f0 + 8)*32 + o],
                                            w2[(k*32 + f0 + 9)*32 + o]);
                if (e == 0) { r.x = b0; r.y = b1; } else { r.z = b0; r.w = b1; }
            }
            g_wfragH[i] = r;
        }
    }
}

// ---------------- stage 1: M=2 nodes per thread, prefetched gather ----------------
__global__ __launch_bounds__(256) void stage1_kernel(
    const float* __restrict__ z_feats,
    const float* __restrict__ w1,
    const float* __restrict__ bn1_gamma,
    const float* __restrict__ bn1_beta,
    const float* __restrict__ bn1_mean,
    const float* __restrict__ bn1_var,
    const float* __restrict__ mlp_w,
    const float* __restrict__ mlp_b,
    const float* __restrict__ mlp_gamma,
    const float* __restrict__ mlp_beta,
    const float* __restrict__ mlp_mean,
    const float* __restrict__ mlp_var)
{
    __shared__ __align__(16) float w1s[KK * FIN * FOUT];
    __shared__ __align__(16) float mws[FIN * FOUT];
    __shared__ float s1[FOUT], t1[FOUT], s2[FOUT], t2[FOUT], mbs[FOUT];

    const int tid = threadIdx.x;
    for (int i = tid; i < KK * FIN * FOUT; i += 256) w1s[i] = w1[i];
    for (int i = tid; i < FIN * FOUT; i += 256) mws[i] = mlp_w[i];
    if (tid < FOUT) {
        float s = bn1_gamma[tid] * rsqrtf(bn1_var[tid] + EPSV);
        s1[tid] = s;
        t1[tid] = bn1_beta[tid] - bn1_mean[tid] * s;
        float q = mlp_gamma[tid] * rsqrtf(mlp_var[tid] + EPSV);
        s2[tid] = q;
        t2[tid] = mlp_beta[tid] - mlp_mean[tid] * q;
        mbs[tid] = mlp_b[tid];
    }
    __syncthreads();

    const int n = (blockIdx.x * 256 + tid) * 2;

    // ---- point branch (2 nodes) ----
    #pragma unroll
    for (int m = 0; m < 2; m++) {
        float acc[FOUT];
        const float zf0 = z_feats[(size_t)(n+m) * 3 + 0];
        const float zf1 = z_feats[(size_t)(n+m) * 3 + 1];
        const float zf2 = z_feats[(size_t)(n+m) * 3 + 2];
        #pragma unroll
        for (int o = 0; o < FOUT; o++) {
            float v = zf0 * mws[o] + zf1 * mws[FOUT + o] + zf2 * mws[2 * FOUT + o] + mbs[o];
            v = v * s2[o] + t2[o];
            acc[o] = fmaxf(v, 0.0f);
        }
        float4* zp = (float4*)&g_z[(size_t)(n+m) * FOUT];
        #pragma unroll
        for (int i = 0; i < 8; i++)
            zp[i] = make_float4(acc[4*i], acc[4*i+1], acc[4*i+2], acc[4*i+3]);
    }

    // ---- voxel branch stage 1, packed f32x2, M=2 reuse, k+1 prefetch ----
    unsigned long long acc0[16], acc1[16];
    #pragma unroll
    for (int i = 0; i < 16; i++) { acc0[i] = 0ull; acc1[i] = 0ull; }

    int2 jj = *(const int2*)(g_nbrT + n);
    float4 xa = __ldg(&g_x4[jj.x]);
    float4 xb = __ldg(&g_x4[jj.y]);

    #pragma unroll 1
    for (int k = 0; k < KK; k++) {
        const float xs0[3] = {xa.x, xa.y, xa.z};
        const float xs1[3] = {xb.x, xb.y, xb.z};
        if (k + 1 < KK) {
            jj = *(const int2*)(g_nbrT + (size_t)(k + 1) * NN + n);
            xa = __ldg(&g_x4[jj.x]);
            xb = __ldg(&g_x4[jj.y]);
        }
        const double2* w = (const double2*)&w1s[k * FIN * FOUT];
        #pragma unroll
        for (int f = 0; f < FIN; f++) {
            unsigned long long hp0, hp1;
            { unsigned int u = __float_as_uint(xs0[f]);
              asm("mov.b64 %0, {%1, %1};" : "=l"(hp0) : "r"(u)); }
            { unsigned int u = __float_as_uint(xs1[f]);
              asm("mov.b64 %0, {%1, %1};" : "=l"(hp1) : "r"(u)); }
            #pragma unroll
            for (int p = 0; p < 8; p++) {
                double2 wv = w[f * 8 + p];
                unsigned long long w0 = __double_as_longlong(wv.x);
                unsigned long long w1v = __double_as_longlong(wv.y);
                asm("fma.rn.f32x2 %0, %1, %2, %0;" : "+l"(acc0[2*p])   : "l"(hp0), "l"(w0));
                asm("fma.rn.f32x2 %0, %1, %2, %0;" : "+l"(acc0[2*p+1]) : "l"(hp0), "l"(w1v));
                asm("fma.rn.f32x2 %0, %1, %2, %0;" : "+l"(acc1[2*p])   : "l"(hp1), "l"(w0));
                asm("fma.rn.f32x2 %0, %1, %2, %0;" : "+l"(acc1[2*p+1]) : "l"(hp1), "l"(w1v));
            }
        }
    }

    // BN + SiLU, round to fp16, write PERMUTED fragment-order 64B rows:
    // chunk m = {hw[m], hw[m+4], hw[m+8], hw[m+12]}
    #pragma unroll
    for (int m = 0; m < 2; m++) {
        const unsigned long long* acc = (m == 0) ? acc0 : acc1;
        uint32_t hw[16];
        #pragma unroll
        for (int p = 0; p < 16; p++) {
            const unsigned long long a = acc[p];
            float v0 = __uint_as_float((unsigned int)(a & 0xffffffffull));
            float v1 = __uint_as_float((unsigned int)(a >> 32));
            const int o0 = 2*p, o1 = 2*p + 1;
            v0 = v0 * s1[o0] + t1[o0]; v0 = v0 / (1.0f + __expf(-v0));
            v1 = v1 * s1[o1] + t1[o1]; v1 = v1 / (1.0f + __expf(-v1));
            hw[p] = pack_h2(v0, v1);
        }
        uint4* row = &g_hh[(size_t)(n+m) * 4];
        row[0] = make_uint4(hw[0], hw[4], hw[8],  hw[12]);
        row[1] = make_uint4(hw[1], hw[5], hw[9],  hw[13]);
        row[2] = make_uint4(hw[2], hw[6], hw[10], hw[14]);
        row[3] = make_uint4(hw[3], hw[7], hw[11], hw[15]);
    }
}

// ---------------- stage 2: direct-fragment LDG.128 mma.sync gather-GEMM ----------------
// No smem/ldmatrix/syncwarp. Lane (r=lane>>2, m=lane&3): ONE LDG.128 per row set s
// (rows s*8+r) at byte m*16 yields {a0_kc0, a2_kc0, a0_kc1, a2_kc1} for that row.
// 4 LDG.128 per warp-k total; double-buffered; indices prefetched one k ahead.

__device__ __forceinline__ void load_rows(uint4 A[4], const int j[4], int m) {
    #pragma unroll
    for (int s = 0; s < 4; s++)
        A[s] = __ldg((const uint4*)((const char*)g_hh + ((size_t)j[s] << 6) + m * 16));
}

__global__ __launch_bounds__(128) void stage2_kernel(
    float* __restrict__ out, size_t half)
{
    const int tid  = threadIdx.x;
    const int warp = tid >> 5;
    const int lane = tid & 31;
    const int tb   = blockIdx.x * 128 + warp * 32;
    const int r = lane >> 2;
    const int m = lane & 3;

    float d[2][4][4];
    #pragma unroll
    for (int t = 0; t < 2; t++)
        #pragma unroll
        for (int nt = 0; nt < 4; nt++)
            #pragma unroll
            for (int e = 0; e < 4; e++) d[t][nt][e] = 0.0f;

    // prologue: idx k=0, idx k=1, A-rows k=0
    int jn[4];
    uint4 A[2][4];
    {
        int jc[4];
        #pragma unroll
        for (int s = 0; s < 4; s++) jc[s] = __ldg(g_nbrT + tb + s * 8 + r);
        #pragma unroll
        for (int s = 0; s < 4; s++) jn[s] = __ldg(g_nbrT + (size_t)NN + tb + s * 8 + r);
        load_rows(A[0], jc, m);
    }

    #pragma unroll 2
    for (int k = 0; k < KK; k++) {
        const int cur = k & 1;
        // issue A-row loads for k+1 (indices already in jn), then idx for k+2
        if (k + 1 < KK) {
            load_rows(A[cur ^ 1], jn, m);
            if (k + 2 < KK) {
                #pragma unroll
                for (int s = 0; s < 4; s++)
                    jn[s] = __ldg(g_nbrT + (size_t)(k + 2) * NN + tb + s * 8 + r);
            }
        }

        // B fragments for this k (4 coalesced LDG.128, L1-resident)
        uint4 bf[4];
        {
            const uint4* wf = g_wfragH + (size_t)k * 128 + lane;
            #pragma unroll
            for (int p = 0; p < 4; p++) bf[p] = __ldg(&wf[p * 32]);
        }

        // 16 MMAs on A[cur]: tile t uses rows A[cur][2t] (a0,a2) / A[cur][2t+1] (a1,a3)
        #pragma unroll
        for (int nt = 0; nt < 4; nt++) {
            const uint4 p0 = bf[nt >> 1];
            const uint32_t b0x = (nt & 1) ? p0.z : p0.x;
            const uint32_t b0y = (nt & 1) ? p0.w : p0.y;
            const uint4 p1 = bf[(4 + nt) >> 1];
            const uint32_t b1x = (nt & 1) ? p1.z : p1.x;
            const uint32_t b1y = (nt & 1) ? p1.w : p1.y;
            #pragma unroll
            for (int t = 0; t < 2; t++) {
                const uint4 v0 = A[cur][2*t];
                const uint4 v1 = A[cur][2*t + 1];
                MMA16816(d[t][nt], v0.x, v1.x, v0.y, v1.y, b0x, b0y);   // kchunk 0
                MMA16816(d[t][nt], v0.z, v1.z, v0.w, v1.w, b1x, b1y);   // kchunk 1
            }
        }
    }

    // epilogue: + z, write both output halves
    const int row  = lane >> 2;
    const int colb = (lane & 3) * 2;
    #pragma unroll
    for (int t = 0; t < 2; t++) {
        const int n0 = tb + t * 16 + row;
        const int n1 = n0 + 8;
        #pragma unroll
        for (int nt = 0; nt < 4; nt++) {
            const int col = nt * 8 + colb;
            const float2 z0 = *(const float2*)(g_z + (size_t)n0 * 32 + col);
            const float2 z1 = *(const float2*)(g_z + (size_t)n1 * 32 + col);
            float2 o0 = make_float2(d[t][nt][0] + z0.x, d[t][nt][1] + z0.y);
            float2 o1 = make_float2(d[t][nt][2] + z1.x, d[t][nt][3] + z1.y);
            *(float2*)(out + (size_t)n0 * 32 + col)        = o0;
            *(float2*)(out + half + (size_t)n0 * 32 + col) = o0;
            *(float2*)(out + (size_t)n1 * 32 + col)        = o1;
            *(float2*)(out + half + (size_t)n1 * 32 + col) = o1;
        }
    }
}

// ---------------------------------------------------------------------------
extern "C" void kernel_launch(void* const* d_in, const int* in_sizes, int n_in,
                              void* d_out, int out_size)
{
    const float* x_feats   = (const float*)d_in[0];
    const float* z_feats   = (const float*)d_in[1];
    const int*   nbr_idx   = (const int*)  d_in[2];
    const float* w1        = (const float*)d_in[3];
    const float* bn1_gamma = (const float*)d_in[4];
    const float* bn1_beta  = (const float*)d_in[5];
    const float* bn1_mean  = (const float*)d_in[6];
    const float* bn1_var   = (const float*)d_in[7];
    const float* w2        = (const float*)d_in[8];
    const float* mlp_w     = (const float*)d_in[9];
    const float* mlp_b     = (const float*)d_in[10];
    const float* mlp_gamma = (const float*)d_in[11];
    const float* mlp_beta  = (const float*)d_in[12];
    const float* mlp_mean  = (const float*)d_in[13];
    const float* mlp_var   = (const float*)d_in[14];

    float* out = (float*)d_out;
    const size_t half = (size_t)out_size / 2;

    prep_kernel<<<NN / 256 + (KK * 128 + 255) / 256, 256>>>(x_feats, nbr_idx, w2);

    stage1_kernel<<<NN / 512, 256>>>(z_feats, w1,
                                     bn1_gamma, bn1_beta, bn1_mean, bn1_var,
                                     mlp_w, mlp_b, mlp_gamma, mlp_beta,
                                     mlp_mean, mlp_var);

    stage2_kernel<<<NN / 128, 128>>>(out, half);
}